// round 16
// baseline (speedup 1.0000x reference)
#include <cuda_runtime.h>
#include <cuda_fp16.h>
#include <math.h>
#include <stdint.h>

#define B_  4
#define T_  2048
#define D_  1024
#define A_  1024
#define V_  1024
#define H_  16
#define DH_ 64
#define QKV_N 3072
#define NEG_ (-10000000000.0f)
#define LOG2E 1.44269504f
#define SC_LOG2E 0.18033688f   // 0.125 * log2(e)

// Scratch (device globals — allocation-free per harness rules)
__device__ __half g_proj [(size_t)B_ * T_ * QKV_N];
__device__ __half g_ctx  [(size_t)B_ * T_ * V_];
__device__ __half g_x16  [(size_t)B_ * T_ * D_];
__device__ __half g_wqkvt[(size_t)QKV_N * D_];
__device__ __half g_woutt[(size_t)D_ * V_];
__device__ float  g_mb   [(size_t)B_ * T_];

// ---------------------------------------------------------------------------
// helpers
// ---------------------------------------------------------------------------
__device__ __forceinline__ float ex2f(float x) {
    float r; asm("ex2.approx.f32 %0, %1;" : "=f"(r) : "f"(x)); return r;
}
__device__ __forceinline__ uint32_t pack_f16(float lo, float hi) {
    uint32_t r;
    asm("cvt.rn.f16x2.f32 %0, %1, %2;" : "=r"(r) : "f"(hi), "f"(lo));
    return r;
}
__device__ __forceinline__ void mma_f16(float* d,
    uint32_t a0, uint32_t a1, uint32_t a2, uint32_t a3, uint32_t b0, uint32_t b1)
{
    asm volatile(
        "mma.sync.aligned.m16n8k16.row.col.f32.f16.f16.f32 "
        "{%0,%1,%2,%3}, {%4,%5,%6,%7}, {%8,%9}, {%0,%1,%2,%3};"
        : "+f"(d[0]), "+f"(d[1]), "+f"(d[2]), "+f"(d[3])
        : "r"(a0), "r"(a1), "r"(a2), "r"(a3), "r"(b0), "r"(b1));
}
__device__ __forceinline__ void ldsm4(uint32_t& r0, uint32_t& r1,
                                      uint32_t& r2, uint32_t& r3, uint32_t addr)
{
    asm volatile("ldmatrix.sync.aligned.m8n8.x4.shared.b16 {%0,%1,%2,%3}, [%4];"
                 : "=r"(r0), "=r"(r1), "=r"(r2), "=r"(r3) : "r"(addr));
}
__device__ __forceinline__ void ldsm4t(uint32_t& r0, uint32_t& r1,
                                       uint32_t& r2, uint32_t& r3, uint32_t addr)
{
    asm volatile("ldmatrix.sync.aligned.m8n8.x4.trans.shared.b16 {%0,%1,%2,%3}, [%4];"
                 : "=r"(r0), "=r"(r1), "=r"(r2), "=r"(r3) : "r"(addr));
}
__device__ __forceinline__ void cp16(uint32_t dst, const void* src) {
    asm volatile("cp.async.cg.shared.global [%0], [%1], 16;" :: "r"(dst), "l"(src));
}
__device__ __forceinline__ void cp_commit() {
    asm volatile("cp.async.commit_group;" ::: "memory");
}
__device__ __forceinline__ void cp_wait0() {
    asm volatile("cp.async.wait_group 0;" ::: "memory");
}

// ---------------------------------------------------------------------------
// fused converters
// ---------------------------------------------------------------------------
__global__ void cvt_x_mask_kernel(const float* __restrict__ x,
                                  __half* __restrict__ x16,
                                  const int* __restrict__ mask,
                                  float* __restrict__ mb,
                                  int nx4, int nmask)
{
    int i = blockIdx.x * blockDim.x + threadIdx.x;
    if (i < nx4) {
        float4 v = ((const float4*)x)[i];
        uint2 u;
        u.x = pack_f16(v.x, v.y);
        u.y = pack_f16(v.z, v.w);
        ((uint2*)x16)[i] = u;
    }
    int j = i - nx4;
    if (j >= 0 && j < nmask)
        mb[j] = (1.0f - (float)mask[j]) * NEG_ * LOG2E;
}

__global__ void cvt_transpose2_fp16(const float* __restrict__ in0, __half* __restrict__ out0,
                                    const float* __restrict__ in1, __half* __restrict__ out1)
{
    __shared__ float tile[32][33];
    const float* in;  __half* out; int R, C;
    if (blockIdx.z == 0) { in = in0; out = out0; R = D_; C = QKV_N; }
    else                 { in = in1; out = out1; R = V_; C = D_; }
    int r0 = blockIdx.y * 32, c0 = blockIdx.x * 32;
    if (r0 >= R || c0 >= C) return;
    int tx = threadIdx.x, ty = threadIdx.y;
#pragma unroll
    for (int i = 0; i < 4; i++)
        tile[ty + i * 8][tx] = in[(size_t)(r0 + ty + i * 8) * C + c0 + tx];
    __syncthreads();
#pragma unroll
    for (int i = 0; i < 4; i++)
        out[(size_t)(c0 + ty + i * 8) * R + r0 + tx] =
            __float2half_rn(tile[tx][ty + i * 8]);
}

// ---------------------------------------------------------------------------
// fp16 GEMM + bias, ldmatrix, 2-stage cp.async pipeline (unchanged)
// ---------------------------------------------------------------------------
#define GS_ROW 20
#define GS_W   (128 * GS_ROW)
#define G_STG_W (2 * GS_W)
#define G_SMEM_BYTES (2 * G_STG_W * 4)   // 40960 B

__global__ __launch_bounds__(256, 2) void gemm_f16(
    const __half* __restrict__ Ag, const __half* __restrict__ Bt,
    const float* __restrict__ bias, __half* __restrict__ out16,
    float* __restrict__ out32, int M, int N, int K)
{
    extern __shared__ uint32_t sm[];
    const uint32_t sbase = (uint32_t)__cvta_generic_to_shared(sm);

    const int tid  = threadIdx.x;
    const int wid  = tid >> 5;
    const int lane = tid & 31;
    const int g    = lane >> 2;
    const int t    = lane & 3;
    const int wm   = (wid >> 1) * 32;
    const int wn   = (wid & 1) * 64;

    const int row0 = blockIdx.y * 128;
    const int col0 = blockIdx.x * 128;

    const int a_lrow = (lane & 15);
    const int a_lcol = (lane >> 4) << 2;
    const int b_lrow = (lane & 7) + ((lane >> 4) << 3);
    const int b_lcol = ((lane >> 3) & 1) << 2;

    auto fill = [&](int s, int k0) {
        uint32_t abase = sbase + (s * G_STG_W) * 4;
        uint32_t bbase = abase + GS_W * 4;
#pragma unroll
        for (int l = 0; l < 2; l++) {
            int f = tid + l * 256;
            int m = f >> 2, c = f & 3;
            cp16(abase + (m * GS_ROW + c * 4) * 4,
                 Ag + (size_t)(row0 + m) * K + k0 + c * 8);
            cp16(bbase + (m * GS_ROW + c * 4) * 4,
                 Bt + (size_t)(col0 + m) * K + k0 + c * 8);
        }
    };

    float acc[2][8][4];
#pragma unroll
    for (int mt = 0; mt < 2; mt++)
#pragma unroll
        for (int nt = 0; nt < 8; nt++)
#pragma unroll
            for (int i = 0; i < 4; i++) acc[mt][nt][i] = 0.0f;

    const int nk = K >> 5;
    fill(0, 0);
    cp_commit();

    for (int it = 0; it < nk; it++) {
        cp_wait0();
        __syncthreads();
        if (it + 1 < nk) { fill((it + 1) & 1, (it + 1) * 32); cp_commit(); }

        uint32_t As = sbase + ((it & 1) * G_STG_W) * 4;
        uint32_t Bs = As + GS_W * 4;

#pragma unroll
        for (int ks = 0; ks < 2; ks++) {
            int kw = ks * 8;
            uint32_t a[2][4];
#pragma unroll
            for (int mt = 0; mt < 2; mt++)
                ldsm4(a[mt][0], a[mt][1], a[mt][2], a[mt][3],
                      As + ((wm + mt * 16 + a_lrow) * GS_ROW + a_lcol + kw) * 4);
#pragma unroll
            for (int ntp = 0; ntp < 4; ntp++) {
                uint32_t b0, b1, b2, b3;
                ldsm4(b0, b1, b2, b3,
                      Bs + ((wn + ntp * 16 + b_lrow) * GS_ROW + b_lcol + kw) * 4);
                mma_f16(acc[0][2 * ntp],     a[0][0], a[0][1], a[0][2], a[0][3], b0, b1);
                mma_f16(acc[1][2 * ntp],     a[1][0], a[1][1], a[1][2], a[1][3], b0, b1);
                mma_f16(acc[0][2 * ntp + 1], a[0][0], a[0][1], a[0][2], a[0][3], b2, b3);
                mma_f16(acc[1][2 * ntp + 1], a[1][0], a[1][1], a[1][2], a[1][3], b2, b3);
            }
        }
    }

#pragma unroll
    for (int nt = 0; nt < 8; nt++) {
        int col = col0 + wn + nt * 8 + 2 * t;
        float bi0 = bias[col];
        float bi1 = bias[col + 1];
#pragma unroll
        for (int mt = 0; mt < 2; mt++) {
            int row = row0 + wm + mt * 16 + g;
            float v00 = acc[mt][nt][0] + bi0, v01 = acc[mt][nt][1] + bi1;
            float v10 = acc[mt][nt][2] + bi0, v11 = acc[mt][nt][3] + bi1;
            if (out16) {
                *(uint32_t*)(out16 + (size_t)row * N + col)       = pack_f16(v00, v01);
                *(uint32_t*)(out16 + (size_t)(row + 8) * N + col) = pack_f16(v10, v11);
            } else {
                *(float2*)(out32 + (size_t)row * N + col)       = make_float2(v00, v01);
                *(float2*)(out32 + (size_t)(row + 8) * N + col) = make_float2(v10, v11);
            }
        }
    }
}

// ---------------------------------------------------------------------------
// fp16 flash attention: Q fragments hoisted to registers (loaded once);
// mainloop processes one 16-key chunk at a time (S -> exp -> PV) so live S
// state is 8 floats. Same FLOPs, same order -> bit-identical output.
// SMEM (words): Qs[128][36] | Ks[64][36]x2 | Vs[64][36]x2 | mb[64]x2
// ---------------------------------------------------------------------------
#define QS_OFF   0
#define KS_OFF(s) (4608 + (s) * 2304)
#define VS_OFF(s) (9216 + (s) * 2304)
#define MB_OFF(s) (13824 + (s) * 64)
#define ATTN_SMEM_BYTES ((13824 + 128) * 4)   // 55,808 B

__global__ __launch_bounds__(256, 2) void attn_f16(
    const __half* __restrict__ proj, const float* __restrict__ mbias,
    __half* __restrict__ ctx)
{
    extern __shared__ uint32_t sm[];
    const uint32_t sbase = (uint32_t)__cvta_generic_to_shared(sm);

    const int tid  = threadIdx.x;
    const int wid  = tid >> 5;
    const int lane = tid & 31;
    const int g    = lane >> 2;
    const int t    = lane & 3;
    const int qw   = wid * 16;

    const int b  = blockIdx.z;
    const int h  = blockIdx.y;
    const int q0 = blockIdx.x * 128;

    const __half* qbase = proj + (size_t)b * T_ * QKV_N + h * DH_;
    const __half* kbase = qbase + A_;
    const __half* vbase = qbase + 2 * A_;
    const float*  mbb   = mbias + b * T_;

    const int a_lrow = (lane & 15);
    const int a_lcol = (lane >> 4) << 2;
    const int b_lrow = (lane & 7) + ((lane >> 4) << 3);
    const int b_lcol = ((lane >> 3) & 1) << 2;
    const int v_krow = (lane & 7) + (((lane >> 3) & 1) << 3);
    const int v_dcol = (lane >> 4) << 2;

    const uint32_t qs_a = sbase + ((qw + a_lrow) * 36 + a_lcol + QS_OFF) * 4;

#pragma unroll
    for (int l = 0; l < 4; l++) {
        int f = tid + l * 256;
        int r = f >> 3, c = f & 7;
        cp16(sbase + (QS_OFF + r * 36 + c * 4) * 4,
             qbase + (size_t)(q0 + r) * QKV_N + c * 8);
    }
    auto fillKV = [&](int s, int kt) {
#pragma unroll
        for (int l = 0; l < 2; l++) {
            int f = tid + l * 256;
            int r = f >> 3, c = f & 7;
            cp16(sbase + (KS_OFF(s) + r * 36 + c * 4) * 4,
                 kbase + (size_t)(kt + r) * QKV_N + c * 8);
            cp16(sbase + (VS_OFF(s) + r * 36 + c * 4) * 4,
                 vbase + (size_t)(kt + r) * QKV_N + c * 8);
        }
        if (tid < 16)
            cp16(sbase + (MB_OFF(s) + tid * 4) * 4, mbb + kt + tid * 4);
    };
    fillKV(0, 0);
    cp_commit();

    float lrow0 = 0.0f, lrow1 = 0.0f;
    float Oacc[8][4];
#pragma unroll
    for (int nt = 0; nt < 8; nt++)
#pragma unroll
        for (int i = 0; i < 4; i++) Oacc[nt][i] = 0.0f;

    uint32_t qf[4][4];   // Q fragments, loaded once at it==0

    const int ntile = T_ / 64;
    for (int it = 0; it < ntile; it++) {
        cp_wait0();
        __syncthreads();
        if (it + 1 < ntile) { fillKV((it + 1) & 1, (it + 1) * 64); cp_commit(); }

        if (it == 0) {
#pragma unroll
            for (int kd = 0; kd < 4; kd++)
                ldsm4(qf[kd][0], qf[kd][1], qf[kd][2], qf[kd][3],
                      qs_a + kd * 8 * 4);
        }

        const int s = it & 1;
        const uint32_t ks_b = sbase + (KS_OFF(s)) * 4;
        const uint32_t vs_b = sbase + (VS_OFF(s)) * 4;
        const float*   mb   = (const float*)(sm + MB_OFF(s));

        // ---- per 16-key chunk: S -> exp -> PV ----
#pragma unroll
        for (int ks = 0; ks < 4; ks++) {
            float S0[4] = {0.f, 0.f, 0.f, 0.f};
            float S1[4] = {0.f, 0.f, 0.f, 0.f};
#pragma unroll
            for (int kd = 0; kd < 4; kd++) {
                uint32_t b0, b1, b2, b3;
                ldsm4(b0, b1, b2, b3,
                      ks_b + ((ks * 16 + b_lrow) * 36 + b_lcol + kd * 8) * 4);
                mma_f16(S0, qf[kd][0], qf[kd][1], qf[kd][2], qf[kd][3], b0, b1);
                mma_f16(S1, qf[kd][0], qf[kd][1], qf[kd][2], qf[kd][3], b2, b3);
            }

            float m0 = mb[ks * 16 + 2 * t];
            float m1 = mb[ks * 16 + 2 * t + 1];
            float m2 = mb[ks * 16 + 8 + 2 * t];
            float m3 = mb[ks * 16 + 8 + 2 * t + 1];
            float p00 = ex2f(fmaf(S0[0], SC_LOG2E, m0));
            float p01 = ex2f(fmaf(S0[1], SC_LOG2E, m1));
            float p02 = ex2f(fmaf(S0[2], SC_LOG2E, m0));
            float p03 = ex2f(fmaf(S0[3], SC_LOG2E, m1));
            float p10 = ex2f(fmaf(S1[0], SC_LOG2E, m2));
            float p11 = ex2f(fmaf(S1[1], SC_LOG2E, m3));
            float p12 = ex2f(fmaf(S1[2], SC_LOG2E, m2));
            float p13 = ex2f(fmaf(S1[3], SC_LOG2E, m3));
            lrow0 += p00 + p01;  lrow1 += p02 + p03;
            lrow0 += p10 + p11;  lrow1 += p12 + p13;

            uint32_t a0 = pack_f16(p00, p01);
            uint32_t a1 = pack_f16(p02, p03);
            uint32_t a2 = pack_f16(p10, p11);
            uint32_t a3 = pack_f16(p12, p13);

#pragma unroll
            for (int ntp = 0; ntp < 4; ntp++) {
                uint32_t b0, b1, b2, b3;
                ldsm4t(b0, b1, b2, b3,
                       vs_b + ((ks * 16 + v_krow) * 36 + ntp * 8 + v_dcol) * 4);
                mma_f16(Oacc[2 * ntp],     a0, a1, a2, a3, b0, b1);
                mma_f16(Oacc[2 * ntp + 1], a0, a1, a2, a3, b2, b3);
            }
        }
    }

    lrow0 += __shfl_xor_sync(0xffffffffu, lrow0, 1);
    lrow0 += __shfl_xor_sync(0xffffffffu, lrow0, 2);
    lrow1 += __shfl_xor_sync(0xffffffffu, lrow1, 1);
    lrow1 += __shfl_xor_sync(0xffffffffu, lrow1, 2);

    float inv0 = 1.0f / lrow0;
    float inv1 = 1.0f / lrow1;
    int rowg = q0 + qw + g;
#pragma unroll
    for (int nt = 0; nt < 8; nt++) {
        int col = h * DH_ + nt * 8 + 2 * t;
        *(uint32_t*)(&ctx[(size_t)(b * T_ + rowg) * V_ + col]) =
            pack_f16(Oacc[nt][0] * inv0, Oacc[nt][1] * inv0);
        *(uint32_t*)(&ctx[(size_t)(b * T_ + rowg + 8) * V_ + col]) =
            pack_f16(Oacc[nt][2] * inv1, Oacc[nt][3] * inv1);
    }
}

// ---------------------------------------------------------------------------
extern "C" void kernel_launch(void* const* d_in, const int* in_sizes, int n_in,
                              void* d_out, int out_size)
{
    const float* x    = (const float*)d_in[0];
    const int*   mask = (const int*)d_in[1];
    const float* Wqkv = (const float*)d_in[2];
    const float* bqkv = (const float*)d_in[3];
    const float* Wout = (const float*)d_in[4];
    const float* bout = (const float*)d_in[5];
    float* out = (float*)d_out;

    __half *proj, *ctx, *x16, *wqkvt, *woutt;
    float *mb;
    cudaGetSymbolAddress((void**)&proj,  g_proj);
    cudaGetSymbolAddress((void**)&ctx,   g_ctx);
    cudaGetSymbolAddress((void**)&x16,   g_x16);
    cudaGetSymbolAddress((void**)&wqkvt, g_wqkvt);
    cudaGetSymbolAddress((void**)&woutt, g_woutt);
    cudaGetSymbolAddress((void**)&mb,    g_mb);

    cudaFuncSetAttribute(gemm_f16,
        cudaFuncAttributeMaxDynamicSharedMemorySize, G_SMEM_BYTES);
    cudaFuncSetAttribute(attn_f16,
        cudaFuncAttributeMaxDynamicSharedMemorySize, ATTN_SMEM_BYTES);

    // 0) converters
    {
        int nx4 = (B_ * T_ * D_) / 4;
        int nmask = B_ * T_;
        int total = nx4 + nmask;
        cvt_x_mask_kernel<<<(total + 255) / 256, 256>>>(x, x16, mask, mb, nx4, nmask);
        dim3 tb(32, 8);
        dim3 tg(QKV_N / 32, D_ / 32, 2);
        cvt_transpose2_fp16<<<tg, tb>>>(Wqkv, wqkvt, Wout, woutt);
    }

    // 1) QKV projection -> fp16 proj
    dim3 g1(QKV_N / 128, (B_ * T_) / 128);
    gemm_f16<<<g1, 256, G_SMEM_BYTES>>>(x16, wqkvt, bqkv, proj, nullptr,
                                        B_ * T_, QKV_N, D_);

    // 2) attention -> fp16 ctx
    dim3 ga(T_ / 128, H_, B_);
    attn_f16<<<ga, 256, ATTN_SMEM_BYTES>>>(proj, mb, ctx);

    // 3) output projection -> fp32 out
    dim3 g2(D_ / 128, (B_ * T_) / 128);
    gemm_f16<<<g2, 256, G_SMEM_BYTES>>>(ctx, woutt, bout, nullptr, out,
                                        B_ * T_, D_, V_);
}

// round 17
// speedup vs baseline: 1.0183x; 1.0183x over previous
#include <cuda_runtime.h>
#include <cuda_fp16.h>
#include <math.h>
#include <stdint.h>

#define B_  4
#define T_  2048
#define D_  1024
#define A_  1024
#define V_  1024
#define H_  16
#define DH_ 64
#define QKV_N 3072
#define NEG_ (-10000000000.0f)
#define LOG2E 1.44269504f
#define SC_LOG2E 0.18033688f   // 0.125 * log2(e)

// Scratch (device globals — allocation-free per harness rules)
__device__ __half g_proj [(size_t)B_ * T_ * QKV_N];
__device__ __half g_ctx  [(size_t)B_ * T_ * V_];
__device__ __half g_x16  [(size_t)B_ * T_ * D_];
__device__ __half g_wqkvt[(size_t)QKV_N * D_];
__device__ __half g_woutt[(size_t)D_ * V_];
__device__ float  g_mb   [(size_t)B_ * T_];

// ---------------------------------------------------------------------------
// helpers
// ---------------------------------------------------------------------------
__device__ __forceinline__ float ex2f(float x) {
    float r; asm("ex2.approx.f32 %0, %1;" : "=f"(r) : "f"(x)); return r;
}
__device__ __forceinline__ uint32_t pack_f16(float lo, float hi) {
    uint32_t r;
    asm("cvt.rn.f16x2.f32 %0, %1, %2;" : "=r"(r) : "f"(hi), "f"(lo));
    return r;
}
__device__ __forceinline__ void mma_f16(float* d,
    uint32_t a0, uint32_t a1, uint32_t a2, uint32_t a3, uint32_t b0, uint32_t b1)
{
    asm volatile(
        "mma.sync.aligned.m16n8k16.row.col.f32.f16.f16.f32 "
        "{%0,%1,%2,%3}, {%4,%5,%6,%7}, {%8,%9}, {%0,%1,%2,%3};"
        : "+f"(d[0]), "+f"(d[1]), "+f"(d[2]), "+f"(d[3])
        : "r"(a0), "r"(a1), "r"(a2), "r"(a3), "r"(b0), "r"(b1));
}
__device__ __forceinline__ void ldsm4(uint32_t& r0, uint32_t& r1,
                                      uint32_t& r2, uint32_t& r3, uint32_t addr)
{
    asm volatile("ldmatrix.sync.aligned.m8n8.x4.shared.b16 {%0,%1,%2,%3}, [%4];"
                 : "=r"(r0), "=r"(r1), "=r"(r2), "=r"(r3) : "r"(addr));
}
__device__ __forceinline__ void ldsm4t(uint32_t& r0, uint32_t& r1,
                                       uint32_t& r2, uint32_t& r3, uint32_t addr)
{
    asm volatile("ldmatrix.sync.aligned.m8n8.x4.trans.shared.b16 {%0,%1,%2,%3}, [%4];"
                 : "=r"(r0), "=r"(r1), "=r"(r2), "=r"(r3) : "r"(addr));
}
__device__ __forceinline__ void cp16(uint32_t dst, const void* src) {
    asm volatile("cp.async.cg.shared.global [%0], [%1], 16;" :: "r"(dst), "l"(src));
}
__device__ __forceinline__ void cp_commit() {
    asm volatile("cp.async.commit_group;" ::: "memory");
}
__device__ __forceinline__ void cp_wait0() {
    asm volatile("cp.async.wait_group 0;" ::: "memory");
}

// ---------------------------------------------------------------------------
// fused converters
// ---------------------------------------------------------------------------
__global__ void cvt_x_mask_kernel(const float* __restrict__ x,
                                  __half* __restrict__ x16,
                                  const int* __restrict__ mask,
                                  float* __restrict__ mb,
                                  int nx4, int nmask)
{
    int i = blockIdx.x * blockDim.x + threadIdx.x;
    if (i < nx4) {
        float4 v = ((const float4*)x)[i];
        uint2 u;
        u.x = pack_f16(v.x, v.y);
        u.y = pack_f16(v.z, v.w);
        ((uint2*)x16)[i] = u;
    }
    int j = i - nx4;
    if (j >= 0 && j < nmask)
        mb[j] = (1.0f - (float)mask[j]) * NEG_ * LOG2E;
}

__global__ void cvt_transpose2_fp16(const float* __restrict__ in0, __half* __restrict__ out0,
                                    const float* __restrict__ in1, __half* __restrict__ out1)
{
    __shared__ float tile[32][33];
    const float* in;  __half* out; int R, C;
    if (blockIdx.z == 0) { in = in0; out = out0; R = D_; C = QKV_N; }
    else                 { in = in1; out = out1; R = V_; C = D_; }
    int r0 = blockIdx.y * 32, c0 = blockIdx.x * 32;
    if (r0 >= R || c0 >= C) return;
    int tx = threadIdx.x, ty = threadIdx.y;
#pragma unroll
    for (int i = 0; i < 4; i++)
        tile[ty + i * 8][tx] = in[(size_t)(r0 + ty + i * 8) * C + c0 + tx];
    __syncthreads();
#pragma unroll
    for (int i = 0; i < 4; i++)
        out[(size_t)(c0 + ty + i * 8) * R + r0 + tx] =
            __float2half_rn(tile[tx][ty + i * 8]);
}

// ---------------------------------------------------------------------------
// fp16 GEMM + bias, ldmatrix, 2-stage cp.async pipeline, BK=64.
// Smem row: 32 data words (64 fp16) + 4 pad = stride 36 (conflict-free).
// ---------------------------------------------------------------------------
#define GS_ROW 36
#define GS_W   (128 * GS_ROW)
#define G_STG_W (2 * GS_W)
#define G_SMEM_BYTES (2 * G_STG_W * 4)   // 73,728 B

__global__ __launch_bounds__(256, 2) void gemm_f16(
    const __half* __restrict__ Ag, const __half* __restrict__ Bt,
    const float* __restrict__ bias, __half* __restrict__ out16,
    float* __restrict__ out32, int M, int N, int K)
{
    extern __shared__ uint32_t sm[];
    const uint32_t sbase = (uint32_t)__cvta_generic_to_shared(sm);

    const int tid  = threadIdx.x;
    const int wid  = tid >> 5;
    const int lane = tid & 31;
    const int g    = lane >> 2;
    const int t    = lane & 3;
    const int wm   = (wid >> 1) * 32;
    const int wn   = (wid & 1) * 64;

    const int row0 = blockIdx.y * 128;
    const int col0 = blockIdx.x * 128;

    const int a_lrow = (lane & 15);
    const int a_lcol = (lane >> 4) << 2;
    const int b_lrow = (lane & 7) + ((lane >> 4) << 3);
    const int b_lcol = ((lane >> 3) & 1) << 2;

    auto fill = [&](int s, int k0) {
        uint32_t abase = sbase + (s * G_STG_W) * 4;
        uint32_t bbase = abase + GS_W * 4;
#pragma unroll
        for (int l = 0; l < 4; l++) {
            int f = tid + l * 256;
            int m = f >> 3, c = f & 7;        // row, 16B chunk (8 fp16)
            cp16(abase + (m * GS_ROW + c * 4) * 4,
                 Ag + (size_t)(row0 + m) * K + k0 + c * 8);
            cp16(bbase + (m * GS_ROW + c * 4) * 4,
                 Bt + (size_t)(col0 + m) * K + k0 + c * 8);
        }
    };

    float acc[2][8][4];
#pragma unroll
    for (int mt = 0; mt < 2; mt++)
#pragma unroll
        for (int nt = 0; nt < 8; nt++)
#pragma unroll
            for (int i = 0; i < 4; i++) acc[mt][nt][i] = 0.0f;

    const int nk = K >> 6;                    // BK = 64
    fill(0, 0);
    cp_commit();

    for (int it = 0; it < nk; it++) {
        cp_wait0();
        __syncthreads();
        if (it + 1 < nk) { fill((it + 1) & 1, (it + 1) * 64); cp_commit(); }

        uint32_t As = sbase + ((it & 1) * G_STG_W) * 4;
        uint32_t Bs = As + GS_W * 4;

#pragma unroll
        for (int ks = 0; ks < 4; ks++) {      // 4 k16 steps
            int kw = ks * 8;
            uint32_t a[2][4];
#pragma unroll
            for (int mt = 0; mt < 2; mt++)
                ldsm4(a[mt][0], a[mt][1], a[mt][2], a[mt][3],
                      As + ((wm + mt * 16 + a_lrow) * GS_ROW + a_lcol + kw) * 4);
#pragma unroll
            for (int ntp = 0; ntp < 4; ntp++) {
                uint32_t b0, b1, b2, b3;
                ldsm4(b0, b1, b2, b3,
                      Bs + ((wn + ntp * 16 + b_lrow) * GS_ROW + b_lcol + kw) * 4);
                mma_f16(acc[0][2 * ntp],     a[0][0], a[0][1], a[0][2], a[0][3], b0, b1);
                mma_f16(acc[1][2 * ntp],     a[1][0], a[1][1], a[1][2], a[1][3], b0, b1);
                mma_f16(acc[0][2 * ntp + 1], a[0][0], a[0][1], a[0][2], a[0][3], b2, b3);
                mma_f16(acc[1][2 * ntp + 1], a[1][0], a[1][1], a[1][2], a[1][3], b2, b3);
            }
        }
    }

#pragma unroll
    for (int nt = 0; nt < 8; nt++) {
        int col = col0 + wn + nt * 8 + 2 * t;
        float bi0 = bias[col];
        float bi1 = bias[col + 1];
#pragma unroll
        for (int mt = 0; mt < 2; mt++) {
            int row = row0 + wm + mt * 16 + g;
            float v00 = acc[mt][nt][0] + bi0, v01 = acc[mt][nt][1] + bi1;
            float v10 = acc[mt][nt][2] + bi0, v11 = acc[mt][nt][3] + bi1;
            if (out16) {
                *(uint32_t*)(out16 + (size_t)row * N + col)       = pack_f16(v00, v01);
                *(uint32_t*)(out16 + (size_t)(row + 8) * N + col) = pack_f16(v10, v11);
            } else {
                *(float2*)(out32 + (size_t)row * N + col)       = make_float2(v00, v01);
                *(float2*)(out32 + (size_t)(row + 8) * N + col) = make_float2(v10, v11);
            }
        }
    }
}

// ---------------------------------------------------------------------------
// fp16 flash attention: 128-key tiles (16 iterations), chunked S->exp->PV
// (16 keys at a time), Q frags hoisted to registers. V natural + trans-LDSM.
// SMEM (words): Qs[128][36] | Ks[128][36]x2 | Vs[128][36]x2 | mb[128]x2
// = 4608 + 9216 + 9216 + 256 = 23,296 words = 93,184 B (2 CTAs = 186KB fits)
// ---------------------------------------------------------------------------
#define QS_OFF   0
#define KS_OFF(s) (4608 + (s) * 4608)
#define VS_OFF(s) (13824 + (s) * 4608)
#define MB_OFF(s) (23040 + (s) * 128)
#define ATTN_SMEM_BYTES ((23040 + 256) * 4)   // 93,184 B

__global__ __launch_bounds__(256, 2) void attn_f16(
    const __half* __restrict__ proj, const float* __restrict__ mbias,
    __half* __restrict__ ctx)
{
    extern __shared__ uint32_t sm[];
    const uint32_t sbase = (uint32_t)__cvta_generic_to_shared(sm);

    const int tid  = threadIdx.x;
    const int wid  = tid >> 5;
    const int lane = tid & 31;
    const int g    = lane >> 2;
    const int t    = lane & 3;
    const int qw   = wid * 16;

    const int b  = blockIdx.z;
    const int h  = blockIdx.y;
    const int q0 = blockIdx.x * 128;

    const __half* qbase = proj + (size_t)b * T_ * QKV_N + h * DH_;
    const __half* kbase = qbase + A_;
    const __half* vbase = qbase + 2 * A_;
    const float*  mbb   = mbias + b * T_;

    const int a_lrow = (lane & 15);
    const int a_lcol = (lane >> 4) << 2;
    const int b_lrow = (lane & 7) + ((lane >> 4) << 3);
    const int b_lcol = ((lane >> 3) & 1) << 2;
    const int v_krow = (lane & 7) + (((lane >> 3) & 1) << 3);
    const int v_dcol = (lane >> 4) << 2;

    const uint32_t qs_a = sbase + ((qw + a_lrow) * 36 + a_lcol + QS_OFF) * 4;

#pragma unroll
    for (int l = 0; l < 4; l++) {
        int f = tid + l * 256;
        int r = f >> 3, c = f & 7;
        cp16(sbase + (QS_OFF + r * 36 + c * 4) * 4,
             qbase + (size_t)(q0 + r) * QKV_N + c * 8);
    }
    auto fillKV = [&](int s, int kt) {
#pragma unroll
        for (int l = 0; l < 4; l++) {
            int f = tid + l * 256;
            int r = f >> 3, c = f & 7;        // key row (0..127), 16B chunk
            cp16(sbase + (KS_OFF(s) + r * 36 + c * 4) * 4,
                 kbase + (size_t)(kt + r) * QKV_N + c * 8);
            cp16(sbase + (VS_OFF(s) + r * 36 + c * 4) * 4,
                 vbase + (size_t)(kt + r) * QKV_N + c * 8);
        }
        if (tid < 32)
            cp16(sbase + (MB_OFF(s) + tid * 4) * 4, mbb + kt + tid * 4);
    };
    fillKV(0, 0);
    cp_commit();

    float lrow0 = 0.0f, lrow1 = 0.0f;
    float Oacc[8][4];
#pragma unroll
    for (int nt = 0; nt < 8; nt++)
#pragma unroll
        for (int i = 0; i < 4; i++) Oacc[nt][i] = 0.0f;

    uint32_t qf[4][4];   // Q fragments, loaded once

    const int ntile = T_ / 128;               // 16 iterations
    for (int it = 0; it < ntile; it++) {
        cp_wait0();
        __syncthreads();
        if (it + 1 < ntile) { fillKV((it + 1) & 1, (it + 1) * 128); cp_commit(); }

        if (it == 0) {
#pragma unroll
            for (int kd = 0; kd < 4; kd++)
                ldsm4(qf[kd][0], qf[kd][1], qf[kd][2], qf[kd][3],
                      qs_a + kd * 8 * 4);
        }

        const int s = it & 1;
        const uint32_t ks_b = sbase + (KS_OFF(s)) * 4;
        const uint32_t vs_b = sbase + (VS_OFF(s)) * 4;
        const float*   mb   = (const float*)(sm + MB_OFF(s));

        // ---- per 16-key chunk: S -> exp -> PV  (8 chunks per tile) ----
#pragma unroll
        for (int ks = 0; ks < 8; ks++) {
            float S0[4] = {0.f, 0.f, 0.f, 0.f};
            float S1[4] = {0.f, 0.f, 0.f, 0.f};
#pragma unroll
            for (int kd = 0; kd < 4; kd++) {
                uint32_t b0, b1, b2, b3;
                ldsm4(b0, b1, b2, b3,
                      ks_b + ((ks * 16 + b_lrow) * 36 + b_lcol + kd * 8) * 4);
                mma_f16(S0, qf[kd][0], qf[kd][1], qf[kd][2], qf[kd][3], b0, b1);
                mma_f16(S1, qf[kd][0], qf[kd][1], qf[kd][2], qf[kd][3], b2, b3);
            }

            float m0 = mb[ks * 16 + 2 * t];
            float m1 = mb[ks * 16 + 2 * t + 1];
            float m2 = mb[ks * 16 + 8 + 2 * t];
            float m3 = mb[ks * 16 + 8 + 2 * t + 1];
            float p00 = ex2f(fmaf(S0[0], SC_LOG2E, m0));
            float p01 = ex2f(fmaf(S0[1], SC_LOG2E, m1));
            float p02 = ex2f(fmaf(S0[2], SC_LOG2E, m0));
            float p03 = ex2f(fmaf(S0[3], SC_LOG2E, m1));
            float p10 = ex2f(fmaf(S1[0], SC_LOG2E, m2));
            float p11 = ex2f(fmaf(S1[1], SC_LOG2E, m3));
            float p12 = ex2f(fmaf(S1[2], SC_LOG2E, m2));
            float p13 = ex2f(fmaf(S1[3], SC_LOG2E, m3));
            lrow0 += p00 + p01;  lrow1 += p02 + p03;
            lrow0 += p10 + p11;  lrow1 += p12 + p13;

            uint32_t a0 = pack_f16(p00, p01);
            uint32_t a1 = pack_f16(p02, p03);
            uint32_t a2 = pack_f16(p10, p11);
            uint32_t a3 = pack_f16(p12, p13);

#pragma unroll
            for (int ntp = 0; ntp < 4; ntp++) {
                uint32_t b0, b1, b2, b3;
                ldsm4t(b0, b1, b2, b3,
                       vs_b + ((ks * 16 + v_krow) * 36 + ntp * 8 + v_dcol) * 4);
                mma_f16(Oacc[2 * ntp],     a0, a1, a2, a3, b0, b1);
                mma_f16(Oacc[2 * ntp + 1], a0, a1, a2, a3, b2, b3);
            }
        }
    }

    lrow0 += __shfl_xor_sync(0xffffffffu, lrow0, 1);
    lrow0 += __shfl_xor_sync(0xffffffffu, lrow0, 2);
    lrow1 += __shfl_xor_sync(0xffffffffu, lrow1, 1);
    lrow1 += __shfl_xor_sync(0xffffffffu, lrow1, 2);

    float inv0 = 1.0f / lrow0;
    float inv1 = 1.0f / lrow1;
    int rowg = q0 + qw + g;
#pragma unroll
    for (int nt = 0; nt < 8; nt++) {
        int col = h * DH_ + nt * 8 + 2 * t;
        *(uint32_t*)(&ctx[(size_t)(b * T_ + rowg) * V_ + col]) =
            pack_f16(Oacc[nt][0] * inv0, Oacc[nt][1] * inv0);
        *(uint32_t*)(&ctx[(size_t)(b * T_ + rowg + 8) * V_ + col]) =
            pack_f16(Oacc[nt][2] * inv1, Oacc[nt][3] * inv1);
    }
}

// ---------------------------------------------------------------------------
extern "C" void kernel_launch(void* const* d_in, const int* in_sizes, int n_in,
                              void* d_out, int out_size)
{
    const float* x    = (const float*)d_in[0];
    const int*   mask = (const int*)d_in[1];
    const float* Wqkv = (const float*)d_in[2];
    const float* bqkv = (const float*)d_in[3];
    const float* Wout = (const float*)d_in[4];
    const float* bout = (const float*)d_in[5];
    float* out = (float*)d_out;

    __half *proj, *ctx, *x16, *wqkvt, *woutt;
    float *mb;
    cudaGetSymbolAddress((void**)&proj,  g_proj);
    cudaGetSymbolAddress((void**)&ctx,   g_ctx);
    cudaGetSymbolAddress((void**)&x16,   g_x16);
    cudaGetSymbolAddress((void**)&wqkvt, g_wqkvt);
    cudaGetSymbolAddress((void**)&woutt, g_woutt);
    cudaGetSymbolAddress((void**)&mb,    g_mb);

    cudaFuncSetAttribute(gemm_f16,
        cudaFuncAttributeMaxDynamicSharedMemorySize, G_SMEM_BYTES);
    cudaFuncSetAttribute(attn_f16,
        cudaFuncAttributeMaxDynamicSharedMemorySize, ATTN_SMEM_BYTES);

    // 0) converters
    {
        int nx4 = (B_ * T_ * D_) / 4;
        int nmask = B_ * T_;
        int total = nx4 + nmask;
        cvt_x_mask_kernel<<<(total + 255) / 256, 256>>>(x, x16, mask, mb, nx4, nmask);
        dim3 tb(32, 8);
        dim3 tg(QKV_N / 32, D_ / 32, 2);
        cvt_transpose2_fp16<<<tg, tb>>>(Wqkv, wqkvt, Wout, woutt);
    }

    // 1) QKV projection -> fp16 proj
    dim3 g1(QKV_N / 128, (B_ * T_) / 128);
    gemm_f16<<<g1, 256, G_SMEM_BYTES>>>(x16, wqkvt, bqkv, proj, nullptr,
                                        B_ * T_, QKV_N, D_);

    // 2) attention -> fp16 ctx
    dim3 ga(T_ / 128, H_, B_);
    attn_f16<<<ga, 256, ATTN_SMEM_BYTES>>>(proj, mb, ctx);

    // 3) output projection -> fp32 out
    dim3 g2(D_ / 128, (B_ * T_) / 128);
    gemm_f16<<<g2, 256, G_SMEM_BYTES>>>(ctx, woutt, bout, nullptr, out,
                                        B_ * T_, D_, V_);
}